// round 11
// baseline (speedup 1.0000x reference)
#include <cuda_runtime.h>
#include <math.h>
#include <stdint.h>

#define SEQ 4096
#define DIM 1024
#define NH  16
#define HDIM 64

// Scratch (tf32 bits stored as float unless noted)
__device__ float g_q[NH * SEQ * HDIM];   // [h][s][hd] tf32, pre-scaled
__device__ float g_k[NH * SEQ * HDIM];   // [h][s][hd] tf32
__device__ float g_v[NH * SEQ * HDIM];   // [h][s][hd] tf32
__device__ float g_att[SEQ * DIM];       // [s][d]     tf32 (combined)
__device__ float g_xt[SEQ * DIM];        // x as tf32
__device__ float g_wq[DIM * DIM];        // weights as tf32
__device__ float g_wk[DIM * DIM];
__device__ float g_wv[DIM * DIM];
__device__ float g_wo[DIM * DIM];
// split-K partials (raw fp32)
__device__ float g_p0[SEQ * DIM];
__device__ float g_p1[SEQ * DIM];
__device__ float g_m0[NH * SEQ];
__device__ float g_l0[NH * SEQ];
__device__ float g_m1[NH * SEQ];
__device__ float g_l1[NH * SEQ];

#define QSCALE (0.125f * 1.4426950408889634f)   // 1/sqrt(64) * log2(e)
#define MINIT  (-1.6e38f)
#define MMASK  (-3.2e38f)

__device__ __forceinline__ uint32_t f2t(float f) {
    uint32_t u;
    asm("cvt.rna.tf32.f32 %0, %1;" : "=r"(u) : "f"(f));
    return u;
}

__device__ __forceinline__ float ex2(float x) {
    float r;
    asm("ex2.approx.f32 %0, %1;" : "=f"(r) : "f"(x));
    return r;
}

__device__ __forceinline__ void mma8(float c[4],
    uint32_t a0, uint32_t a1, uint32_t a2, uint32_t a3,
    uint32_t b0, uint32_t b1)
{
    asm volatile(
        "mma.sync.aligned.m16n8k8.row.col.f32.tf32.tf32.f32 "
        "{%0,%1,%2,%3},{%4,%5,%6,%7},{%8,%9},{%0,%1,%2,%3};"
        : "+f"(c[0]), "+f"(c[1]), "+f"(c[2]), "+f"(c[3])
        : "r"(a0), "r"(a1), "r"(a2), "r"(a3), "r"(b0), "r"(b1));
}

__device__ __forceinline__ void cpa16(uint32_t dst_smem, const void* src) {
    asm volatile("cp.async.cg.shared.global [%0], [%1], 16;"
                 :: "r"(dst_smem), "l"(src));
}
__device__ __forceinline__ void cpa_commit() {
    asm volatile("cp.async.commit_group;");
}
template<int N>
__device__ __forceinline__ void cpa_wait() {
    asm volatile("cp.async.wait_group %0;" :: "n"(N));
}

// ---------------------------------------------------------------------------
// Convert fp32 -> tf32 bits
// ---------------------------------------------------------------------------
__global__ void cvt_tf32(const float* __restrict__ src, float* __restrict__ dst,
                         int n4)
{
    for (int i = blockIdx.x * blockDim.x + threadIdx.x; i < n4;
         i += gridDim.x * blockDim.x) {
        float4 v = ((const float4*)src)[i];
        v.x = __uint_as_float(f2t(v.x));
        v.y = __uint_as_float(f2t(v.y));
        v.z = __uint_as_float(f2t(v.z));
        v.w = __uint_as_float(f2t(v.w));
        ((float4*)dst)[i] = v;
    }
}

__global__ void cvt_tf32_w(const float* __restrict__ s0, float* __restrict__ d0,
                           const float* __restrict__ s1, float* __restrict__ d1,
                           const float* __restrict__ s2, float* __restrict__ d2,
                           const float* __restrict__ s3, float* __restrict__ d3,
                           int n4)
{
    const float* src; float* dst;
    if (blockIdx.z == 0)      { src = s0; dst = d0; }
    else if (blockIdx.z == 1) { src = s1; dst = d1; }
    else if (blockIdx.z == 2) { src = s2; dst = d2; }
    else                      { src = s3; dst = d3; }
    for (int i = blockIdx.x * blockDim.x + threadIdx.x; i < n4;
         i += gridDim.x * blockDim.x) {
        float4 v = ((const float4*)src)[i];
        v.x = __uint_as_float(f2t(v.x));
        v.y = __uint_as_float(f2t(v.y));
        v.z = __uint_as_float(f2t(v.z));
        v.w = __uint_as_float(f2t(v.w));
        ((float4*)dst)[i] = v;
    }
}

// ---------------------------------------------------------------------------
// TF32 GEMM (mma.sync), 64x64 warp tiles, 128 threads (2x2 warps),
// BK=32, 3-stage cp.async, ONE barrier per chunk.   (unchanged from R10)
// ---------------------------------------------------------------------------
#define GBK   32
#define GSAS  36
#define GSTW  (128 * GSAS)
#define GSTB  (2 * GSTW * 4)
#define GSMEM (3 * GSTB)

__global__ void __launch_bounds__(128) gemm_tf32(
    const float* __restrict__ A,
    const float* __restrict__ W0, const float* __restrict__ W1,
    const float* __restrict__ W2,
    float* __restrict__ out0, float* __restrict__ out1,
    float* __restrict__ out2,
    const float* __restrict__ cosT, const float* __restrict__ sinT,
    int mode0)
{
    extern __shared__ uint32_t gsm[];

    const float* W; float* out; int mode;
    if (blockIdx.z == 0)      { W = W0; out = out0; mode = mode0; }
    else if (blockIdx.z == 1) { W = W1; out = out1; mode = 2; }
    else                      { W = W2; out = out2; mode = 3; }

    const int tid  = threadIdx.x;
    const int lane = tid & 31;
    const int wid  = tid >> 5;
    const int wm   = wid >> 1;
    const int wn   = wid & 1;
    const int g4   = lane >> 2;
    const int t4   = lane & 3;

    const int mBase = blockIdx.y * 128;
    const int nBase = blockIdx.x * 128;

    const uint32_t smemu = (uint32_t)__cvta_generic_to_shared(gsm);

    auto prefetch = [&](int s, int t) {
        const int koff = t * GBK;
        const uint32_t abase = smemu + s * GSTB;
        const uint32_t bbase = abase + GSTW * 4;
#pragma unroll
        for (int j = 0; j < 8; j++) {
            const int idx = tid + j * 128;
            const int r = idx >> 3, c4 = (idx & 7) << 2;
            cpa16(abase + (r * GSAS + c4) * 4, A + (size_t)(mBase + r) * DIM + koff + c4);
            cpa16(bbase + (r * GSAS + c4) * 4, W + (size_t)(nBase + r) * DIM + koff + c4);
        }
    };

    float c[4][8][4];
#pragma unroll
    for (int mt = 0; mt < 4; mt++)
#pragma unroll
        for (int nt = 0; nt < 8; nt++)
#pragma unroll
            for (int i = 0; i < 4; i++) c[mt][nt][i] = 0.f;

    const int NT = DIM / GBK;
    prefetch(0, 0); cpa_commit();
    prefetch(1, 1); cpa_commit();

    for (int t = 0; t < NT; t++) {
        if (t + 1 < NT) cpa_wait<1>(); else cpa_wait<0>();
        __syncthreads();

        if (t + 2 < NT) { prefetch((t + 2) % 3, t + 2); cpa_commit(); }

        const uint32_t* a_s = gsm + (t % 3) * (GSTB / 4);
        const uint32_t* b_s = a_s + GSTW;
#pragma unroll
        for (int ks = 0; ks < 4; ks++) {
            const int kk = ks * 8 + t4;
            uint32_t af[4][4], bf[8][2];
#pragma unroll
            for (int mt = 0; mt < 4; mt++) {
                const int r = wm * 64 + mt * 16 + g4;
                af[mt][0] = a_s[r * GSAS + kk];
                af[mt][1] = a_s[(r + 8) * GSAS + kk];
                af[mt][2] = a_s[r * GSAS + kk + 4];
                af[mt][3] = a_s[(r + 8) * GSAS + kk + 4];
            }
#pragma unroll
            for (int nt = 0; nt < 8; nt++) {
                const int r = wn * 64 + nt * 8 + g4;
                bf[nt][0] = b_s[r * GSAS + kk];
                bf[nt][1] = b_s[r * GSAS + kk + 4];
            }
#pragma unroll
            for (int mt = 0; mt < 4; mt++)
#pragma unroll
                for (int nt = 0; nt < 8; nt++)
                    mma8(c[mt][nt], af[mt][0], af[mt][1], af[mt][2], af[mt][3],
                         bf[nt][0], bf[nt][1]);
        }
    }

#pragma unroll
    for (int mt = 0; mt < 4; mt++) {
        const int r0 = mBase + wm * 64 + mt * 16 + g4;
#pragma unroll
        for (int nt = 0; nt < 8; nt++) {
            const int colg = nBase + wn * 64 + nt * 8 + (t4 << 1);
            const float* cc = c[mt][nt];
            if (mode == 0) {
                *(float2*)(out + (size_t)r0 * DIM + colg)       = make_float2(cc[0], cc[1]);
                *(float2*)(out + (size_t)(r0 + 8) * DIM + colg) = make_float2(cc[2], cc[3]);
            } else {
                const int head = colg >> 6;
                const int hd   = colg & 63;
                const int f    = hd >> 1;
#pragma unroll
                for (int h = 0; h < 2; h++) {
                    const int row = r0 + h * 8;
                    float e = cc[h * 2 + 0], o = cc[h * 2 + 1];
                    float re = e, ro = o;
                    if (mode != 3) {
                        const float cth = cosT[row * 32 + f];
                        const float sth = sinT[row * 32 + f];
                        re = e * cth - o * sth;
                        ro = e * sth + o * cth;
                        if (mode == 1) { re *= QSCALE; ro *= QSCALE; }
                    }
                    float* dst = out + ((size_t)head * SEQ + row) * HDIM + hd;
                    dst[0] = __uint_as_float(f2t(re));
                    dst[1] = __uint_as_float(f2t(ro));
                }
            }
        }
    }
}

// ---------------------------------------------------------------------------
// Split-K TF32 flash attention. Each (qblk, head) handled by 2 CTAs, one per
// half of the key range. Partial (unnormalized O, m, l) written to global;
// flash_combine merges. blockIdx.x encodes (qblk, split), longest first.
// M=32 warp tile, 32-key tiles, Q fragment-major in smem.
// ---------------------------------------------------------------------------
#define FP  68
#define VP  72
#define KT  32
#define SQF_W  8192
#define STAGE_W (KT * FP + KT * VP)
#define FLASH_SMEM ((SQF_W + 2 * STAGE_W) * (int)sizeof(uint32_t))

__global__ void __launch_bounds__(128, 3) flash_split(
    const float* __restrict__ Q, const float* __restrict__ K,
    const float* __restrict__ V,
    float* __restrict__ p0, float* __restrict__ p1,
    float* __restrict__ gm0, float* __restrict__ gl0,
    float* __restrict__ gm1, float* __restrict__ gl1)
{
    extern __shared__ uint32_t fsm[];
    uint32_t* sQf = fsm;

    const int tid  = threadIdx.x;
    const int lane = tid & 31;
    const int wid  = tid >> 5;
    const int g4   = lane >> 2;
    const int t4   = lane & 3;

    const int enc  = gridDim.x - 1 - blockIdx.x;   // longest first
    const int qblk = enc >> 1;
    const int split = enc & 1;
    const int head = blockIdx.y;

    float* part = split ? p1 : p0;
    float* gm   = split ? gm1 : gm0;
    float* gl   = split ? gl1 : gl0;

    const uint32_t smemu = (uint32_t)__cvta_generic_to_shared(fsm);
    const float* Kh0 = K + (size_t)head * SEQ * HDIM;
    const float* Vh0 = V + (size_t)head * SEQ * HDIM;

    auto prefetch = [&](int buf, int kb) {
        const uint32_t base = smemu + (SQF_W + buf * STAGE_W) * 4;
        const float* Kh = Kh0 + (size_t)kb * KT * HDIM;
        const float* Vh = Vh0 + (size_t)kb * KT * HDIM;
#pragma unroll
        for (int j = 0; j < 4; j++) {
            const int idx = tid + j * 128;
            const int r = idx >> 4, c4 = (idx & 15) << 2;
            cpa16(base + (r * FP + c4) * 4, Kh + r * HDIM + c4);
            cpa16(base + (KT * FP + r * VP + c4) * 4, Vh + r * HDIM + c4);
        }
    };

    const int half = 2 * (qblk + 1);     // 32-key tiles per split
    const int t0 = split * half;
    const int t1 = t0 + half;            // t0 even -> (kb & 1) buffer parity ok

    prefetch(0, t0); cpa_commit();
    prefetch(1, t0 + 1); cpa_commit();   // half >= 2 always

    // ---- repack Q (128 x 64) into fragment-major layout (one time) ----
    {
        const float* Qh = Q + ((size_t)head * SEQ + qblk * 128) * HDIM;
#pragma unroll
        for (int j = 0; j < 16; j++) {
            const int idx = tid + j * 128;
            const int r = idx >> 4, c4 = (idx & 15) << 2;
            float4 v = *(const float4*)(Qh + (size_t)r * HDIM + c4);
            const int widr = r >> 5, mh = (r >> 4) & 1, g4r = r & 7;
            const int rowH = (r >> 3) & 1;
            const int kk = c4 >> 3, colH = (c4 >> 2) & 1;
            const int s = rowH + 2 * colH;
            uint32_t* dst = sQf + (((widr * 8 + kk) * 2 + mh) * 8 + g4r) * 16 + s;
            dst[0]  = __float_as_uint(v.x);
            dst[4]  = __float_as_uint(v.y);
            dst[8]  = __float_as_uint(v.z);
            dst[12] = __float_as_uint(v.w);
        }
    }

    float o[2][8][4];
#pragma unroll
    for (int mh = 0; mh < 2; mh++)
#pragma unroll
        for (int nt = 0; nt < 8; nt++)
#pragma unroll
            for (int i = 0; i < 4; i++) o[mh][nt][i] = 0.f;

    float m[2][2], l[2][2];
#pragma unroll
    for (int mh = 0; mh < 2; mh++) {
        m[mh][0] = MINIT; m[mh][1] = MINIT;
        l[mh][0] = 0.f;   l[mh][1] = 0.f;
    }

    const int srcA = (lane & 28) | (t4 >> 1);
    const int srcB = srcA + 2;
    const bool odd = (t4 & 1);

    __syncthreads();   // Q repack visible to all warps

    const uint32_t* qbase = sQf + wid * 2048 + g4 * 16 + t4 * 4;

    for (int kb = t0; kb < t1; kb++) {
        if (kb + 1 < t1) cpa_wait<1>(); else cpa_wait<0>();
        __syncthreads();

        const uint32_t* sK = fsm + SQF_W + (kb & 1) * STAGE_W;
        const uint32_t* sV = sK + KT * FP;

        // ---- S = Q K^T ----
        float sc[2][4][4];
#pragma unroll
        for (int mh = 0; mh < 2; mh++)
#pragma unroll
            for (int nt = 0; nt < 4; nt++)
#pragma unroll
                for (int i = 0; i < 4; i++) sc[mh][nt][i] = 0.f;

        const uint32_t* kbase = sK + g4 * FP + t4;
#pragma unroll
        for (int kk = 0; kk < 8; kk++) {
            const uint4 qa0 = *(const uint4*)(qbase + kk * 256);
            const uint4 qa1 = *(const uint4*)(qbase + kk * 256 + 128);
#pragma unroll
            for (int nt = 0; nt < 4; nt++) {
                const uint32_t* bp = kbase + nt * 8 * FP + kk * 8;
                const uint32_t b0 = bp[0], b1 = bp[4];
                mma8(sc[0][nt], qa0.x, qa0.y, qa0.z, qa0.w, b0, b1);
                mma8(sc[1][nt], qa1.x, qa1.y, qa1.z, qa1.w, b0, b1);
            }
        }

        // ---- causal mask (tiles intersecting the diagonal; global kb) ----
        if (kb >= 4 * qblk) {
#pragma unroll
            for (int mh = 0; mh < 2; mh++) {
                const int r0 = qblk * 128 + wid * 32 + mh * 16 + g4;
                const int r1 = r0 + 8;
#pragma unroll
                for (int nt = 0; nt < 4; nt++) {
                    const int col = kb * KT + nt * 8 + (t4 << 1);
                    if (col > r0)     sc[mh][nt][0] = MMASK;
                    if (col + 1 > r0) sc[mh][nt][1] = MMASK;
                    if (col > r1)     sc[mh][nt][2] = MMASK;
                    if (col + 1 > r1) sc[mh][nt][3] = MMASK;
                }
            }
        }

        // ---- online softmax (log2 domain, finite sentinels) ----
        float corr[2][2];
#pragma unroll
        for (int mh = 0; mh < 2; mh++) {
            float mx0 = MMASK, mx1 = MMASK;
#pragma unroll
            for (int nt = 0; nt < 4; nt++) {
                mx0 = fmaxf(mx0, fmaxf(sc[mh][nt][0], sc[mh][nt][1]));
                mx1 = fmaxf(mx1, fmaxf(sc[mh][nt][2], sc[mh][nt][3]));
            }
            mx0 = fmaxf(mx0, __shfl_xor_sync(0xffffffffu, mx0, 1));
            mx0 = fmaxf(mx0, __shfl_xor_sync(0xffffffffu, mx0, 2));
            mx1 = fmaxf(mx1, __shfl_xor_sync(0xffffffffu, mx1, 1));
            mx1 = fmaxf(mx1, __shfl_xor_sync(0xffffffffu, mx1, 2));

            const float mn0 = fmaxf(m[mh][0], mx0);
            const float mn1 = fmaxf(m[mh][1], mx1);
            corr[mh][0] = ex2(m[mh][0] - mn0);
            corr[mh][1] = ex2(m[mh][1] - mn1);
            m[mh][0] = mn0; m[mh][1] = mn1;

            float ls0 = 0.f, ls1 = 0.f;
#pragma unroll
            for (int nt = 0; nt < 4; nt++) {
                sc[mh][nt][0] = ex2(sc[mh][nt][0] - mn0);
                sc[mh][nt][1] = ex2(sc[mh][nt][1] - mn0);
                sc[mh][nt][2] = ex2(sc[mh][nt][2] - mn1);
                sc[mh][nt][3] = ex2(sc[mh][nt][3] - mn1);
                ls0 += sc[mh][nt][0] + sc[mh][nt][1];
                ls1 += sc[mh][nt][2] + sc[mh][nt][3];
            }
            ls0 += __shfl_xor_sync(0xffffffffu, ls0, 1);
            ls0 += __shfl_xor_sync(0xffffffffu, ls0, 2);
            ls1 += __shfl_xor_sync(0xffffffffu, ls1, 1);
            ls1 += __shfl_xor_sync(0xffffffffu, ls1, 2);
            l[mh][0] = l[mh][0] * corr[mh][0] + ls0;
            l[mh][1] = l[mh][1] * corr[mh][1] + ls1;

#pragma unroll
            for (int nt = 0; nt < 8; nt++) {
                o[mh][nt][0] *= corr[mh][0]; o[mh][nt][1] *= corr[mh][0];
                o[mh][nt][2] *= corr[mh][1]; o[mh][nt][3] *= corr[mh][1];
            }
        }

        // ---- O += P V ----
        const uint32_t* vbase = sV + t4 * VP + g4;
#pragma unroll
        for (int kk = 0; kk < 4; kk++) {
            uint32_t pa[2][4];
#pragma unroll
            for (int mh = 0; mh < 2; mh++) {
                const float v0 = __shfl_sync(0xffffffffu, sc[mh][kk][0], srcA);
                const float v1 = __shfl_sync(0xffffffffu, sc[mh][kk][1], srcA);
                const float v2 = __shfl_sync(0xffffffffu, sc[mh][kk][2], srcA);
                const float v3 = __shfl_sync(0xffffffffu, sc[mh][kk][3], srcA);
                const float v4 = __shfl_sync(0xffffffffu, sc[mh][kk][0], srcB);
                const float v5 = __shfl_sync(0xffffffffu, sc[mh][kk][1], srcB);
                const float v6 = __shfl_sync(0xffffffffu, sc[mh][kk][2], srcB);
                const float v7 = __shfl_sync(0xffffffffu, sc[mh][kk][3], srcB);
                pa[mh][0] = f2t(odd ? v1 : v0);
                pa[mh][1] = f2t(odd ? v3 : v2);
                pa[mh][2] = f2t(odd ? v5 : v4);
                pa[mh][3] = f2t(odd ? v7 : v6);
            }
            const uint32_t* vrow = vbase + kk * 8 * VP;
#pragma unroll
            for (int nt = 0; nt < 8; nt++) {
                const uint32_t b0 = vrow[nt * 8];
                const uint32_t b1 = vrow[4 * VP + nt * 8];
                mma8(o[0][nt], pa[0][0], pa[0][1], pa[0][2], pa[0][3], b0, b1);
                mma8(o[1][nt], pa[1][0], pa[1][1], pa[1][2], pa[1][3], b0, b1);
            }
        }

        __syncthreads();
        if (kb + 2 < t1) { prefetch(kb & 1, kb + 2); cpa_commit(); }
    }

    // ---- epilogue: write raw partial O + (m, l) per row ----
#pragma unroll
    for (int mh = 0; mh < 2; mh++) {
        const int r0 = qblk * 128 + wid * 32 + mh * 16 + g4;
#pragma unroll
        for (int nt = 0; nt < 8; nt++) {
            const int col = head * HDIM + nt * 8 + (t4 << 1);
            *(float2*)(part + (size_t)r0 * DIM + col) =
                make_float2(o[mh][nt][0], o[mh][nt][1]);
            *(float2*)(part + (size_t)(r0 + 8) * DIM + col) =
                make_float2(o[mh][nt][2], o[mh][nt][3]);
        }
        if (t4 == 0) {
            gm[head * SEQ + r0]     = m[mh][0];
            gl[head * SEQ + r0]     = l[mh][0];
            gm[head * SEQ + r0 + 8] = m[mh][1];
            gl[head * SEQ + r0 + 8] = l[mh][1];
        }
    }
}

// ---------------------------------------------------------------------------
// Combine: att = (O0*w0 + O1*w1) / (l0*w0 + l1*w1), tf32 bits out.
// ---------------------------------------------------------------------------
__global__ void flash_combine(
    const float* __restrict__ p0, const float* __restrict__ p1,
    const float* __restrict__ gm0, const float* __restrict__ gl0,
    const float* __restrict__ gm1, const float* __restrict__ gl1,
    float* __restrict__ att)
{
    const int n4 = SEQ * DIM / 4;
    for (int i = blockIdx.x * blockDim.x + threadIdx.x; i < n4;
         i += gridDim.x * blockDim.x) {
        const int row  = i >> 8;          // 256 float4 per row
        const int head = (i >> 4) & 15;   // 16 float4 per head
        const int mli  = head * SEQ + row;
        const float m0 = gm0[mli], m1 = gm1[mli];
        const float ms = fmaxf(m0, m1);
        const float w0 = ex2(m0 - ms), w1 = ex2(m1 - ms);
        const float inv = 1.f / (gl0[mli] * w0 + gl1[mli] * w1);
        const float4 a = ((const float4*)p0)[i];
        const float4 b = ((const float4*)p1)[i];
        float4 r;
        r.x = __uint_as_float(f2t((a.x * w0 + b.x * w1) * inv));
        r.y = __uint_as_float(f2t((a.y * w0 + b.y * w1) * inv));
        r.z = __uint_as_float(f2t((a.z * w0 + b.z * w1) * inv));
        r.w = __uint_as_float(f2t((a.w * w0 + b.w * w1) * inv));
        ((float4*)att)[i] = r;
    }
}

// ---------------------------------------------------------------------------
// Launch
// ---------------------------------------------------------------------------
extern "C" void kernel_launch(void* const* d_in, const int* in_sizes, int n_in,
                              void* d_out, int out_size)
{
    const float* x    = (const float*)d_in[0];
    const float* cosT = (const float*)d_in[1];
    const float* sinT = (const float*)d_in[2];
    const float* wq   = (const float*)d_in[4];
    const float* wk   = (const float*)d_in[5];
    const float* wv   = (const float*)d_in[6];
    const float* wo   = (const float*)d_in[7];
    float* out = (float*)d_out;

    float *qp, *kp, *vp, *ap, *xt, *wqt, *wkt, *wvt, *wot;
    float *p0, *p1, *m0, *l0, *m1, *l1;
    cudaGetSymbolAddress((void**)&qp, g_q);
    cudaGetSymbolAddress((void**)&kp, g_k);
    cudaGetSymbolAddress((void**)&vp, g_v);
    cudaGetSymbolAddress((void**)&ap, g_att);
    cudaGetSymbolAddress((void**)&xt, g_xt);
    cudaGetSymbolAddress((void**)&wqt, g_wq);
    cudaGetSymbolAddress((void**)&wkt, g_wk);
    cudaGetSymbolAddress((void**)&wvt, g_wv);
    cudaGetSymbolAddress((void**)&wot, g_wo);
    cudaGetSymbolAddress((void**)&p0, g_p0);
    cudaGetSymbolAddress((void**)&p1, g_p1);
    cudaGetSymbolAddress((void**)&m0, g_m0);
    cudaGetSymbolAddress((void**)&l0, g_l0);
    cudaGetSymbolAddress((void**)&m1, g_m1);
    cudaGetSymbolAddress((void**)&l1, g_l1);

    cudaFuncSetAttribute(flash_split,
                         cudaFuncAttributeMaxDynamicSharedMemorySize, FLASH_SMEM);
    cudaFuncSetAttribute(gemm_tf32,
                         cudaFuncAttributeMaxDynamicSharedMemorySize, GSMEM);

    // Convert inputs to tf32 bits once
    cvt_tf32<<<512, 256>>>(x, xt, SEQ * DIM / 4);
    dim3 wgrid(128, 1, 4);
    cvt_tf32_w<<<wgrid, 256>>>(wq, wqt, wk, wkt, wv, wvt, wo, wot, DIM * DIM / 4);

    // Fused QKV projections (z = 0,1,2 -> Q,K,V)
    dim3 ggrid(DIM / 128, SEQ / 128, 3);
    gemm_tf32<<<ggrid, 128, GSMEM>>>(xt, wqt, wkt, wvt, qp, kp, vp, cosT, sinT, 1);

    // Split-K flash: x encodes (qblk, split), longest pairs first
    dim3 fgrid(2 * (SEQ / 128), NH);
    flash_split<<<fgrid, 128, FLASH_SMEM>>>(qp, kp, vp, p0, p1, m0, l0, m1, l1);

    flash_combine<<<1024, 256>>>(p0, p1, m0, l0, m1, l1, ap);

    // Output projection
    dim3 ogrid(DIM / 128, SEQ / 128, 1);
    gemm_tf32<<<ogrid, 128, GSMEM>>>(ap, wot, wot, wot, out, out, out, cosT, sinT, 0);
}